// round 1
// baseline (speedup 1.0000x reference)
#include <cuda_runtime.h>
#include <math.h>

#define TT   512      // frames per batch (reference setup)
#define NLM  51       // landmarks
#define FPF  114      // features per frame
#define SP   115      // padded smem stride (odd -> conflict-free)
#define BLK  64       // threads per block (1 frame / thread)

__device__ __forceinline__ float3 f3sub(float3 a, float3 b){ return make_float3(a.x-b.x, a.y-b.y, a.z-b.z); }
__device__ __forceinline__ float3 f3add(float3 a, float3 b){ return make_float3(a.x+b.x, a.y+b.y, a.z+b.z); }
__device__ __forceinline__ float3 f3scale(float3 a, float s){ return make_float3(a.x*s, a.y*s, a.z*s); }
__device__ __forceinline__ float  f3dot(float3 a, float3 b){ return a.x*b.x + a.y*b.y + a.z*b.z; }
__device__ __forceinline__ float3 f3cross(float3 a, float3 b){
    return make_float3(a.y*b.z - a.z*b.y, a.z*b.x - a.x*b.z, a.x*b.y - a.y*b.x);
}
__device__ __forceinline__ float f3norm(float3 v){ return sqrtf(f3dot(v,v)); }
// _dist: sqrt(sum + 1e-6)
__device__ __forceinline__ float distE(float3 a, float3 b){ float3 d = f3sub(a,b); return sqrtf(f3dot(d,d) + 1e-6f); }
// _acos with reference clipping
__device__ __forceinline__ float acosc(float c){ return acosf(fminf(fmaxf(c, -1.0f + 1e-6f), 1.0f - 1e-6f)); }

// load one landmark (3 floats) from a frame base pointer
__device__ __forceinline__ float3 loadp(const float* __restrict__ fr, int lm){
    const float* q = fr + lm * 3;
    return make_float3(__ldg(q), __ldg(q + 1), __ldg(q + 2));
}
// load landmark lm at frame tc within batch (xb = batch base)
__device__ __forceinline__ float3 lpt(const float* __restrict__ xb, int tc, int lm){
    const float* q = xb + (size_t)tc * (NLM * 3) + lm * 3;
    return make_float3(__ldg(q), __ldg(q + 1), __ldg(q + 2));
}
// edge-replicated central difference velocity of landmark lm at time t
__device__ __forceinline__ float3 velAt(const float* __restrict__ xb, int t, int lm){
    int tc = t < 1 ? 1 : (t > TT - 2 ? TT - 2 : t);
    float3 a = lpt(xb, tc + 1, lm);
    float3 c = lpt(xb, tc - 1, lm);
    return make_float3(0.5f * (a.x - c.x), 0.5f * (a.y - c.y), 0.5f * (a.z - c.z));
}

// JOINT_TRIPLETS
__constant__ int cP[15] = {0,1,2, 0,5,6, 0,9,10, 0,13,14, 0,17,18};
__constant__ int cJ[15] = {1,2,3, 5,6,7, 9,10,11, 13,14,15, 17,18,19};
__constant__ int cC[15] = {2,3,4, 6,7,8, 10,11,12, 14,15,16, 18,19,20};

__global__ void __launch_bounds__(BLK)
geo_kernel(const float* __restrict__ xyz,
           const float* __restrict__ fmask,
           const float* __restrict__ bmask,
           float* __restrict__ out,
           int BT)
{
    __shared__ float so[BLK * SP];
    const int tid = threadIdx.x;
    const int bt  = blockIdx.x * BLK + tid;

    if (bt < BT) {
        const float* fr = xyz + (size_t)bt * (NLM * 3);
        float* o = so + tid * SP;
        const float fg = __ldg(fmask + bt);
        const float bg = __ldg(bmask + bt);

        // ---- per-hand: tips(5) + curls(5) + cross + d_ti  -> feats [0..23] ----
        #pragma unroll
        for (int h = 0; h < 2; ++h) {
            const int b = h * 21, fo = h * 12;
            float3 tT = loadp(fr, b + 4),  tI = loadp(fr, b + 8),  tM = loadp(fr, b + 12);
            float3 tR = loadp(fr, b + 16), tP = loadp(fr, b + 20);
            o[fo + 0] = distE(tT, tI);
            o[fo + 1] = distE(tI, tM);
            o[fo + 2] = distE(tM, tR);
            o[fo + 3] = distE(tR, tP);
            o[fo + 4] = distE(tT, tP);
            float3 m2  = loadp(fr, b + 2),  m5  = loadp(fr, b + 5),  m9  = loadp(fr, b + 9);
            float3 m13 = loadp(fr, b + 13), m17 = loadp(fr, b + 17);
            float3 i3  = loadp(fr, b + 3),  i6  = loadp(fr, b + 6),  i10 = loadp(fr, b + 10);
            float3 i14 = loadp(fr, b + 14), i18 = loadp(fr, b + 18);
            o[fo + 5] = distE(m2,  tT) / (distE(m2,  i3)  + 1e-4f);
            o[fo + 6] = distE(m5,  tI) / (distE(m5,  i6)  + 1e-4f);
            o[fo + 7] = distE(m9,  tM) / (distE(m9,  i10) + 1e-4f);
            o[fo + 8] = distE(m13, tR) / (distE(m13, i14) + 1e-4f);
            o[fo + 9] = distE(m17, tP) / (distE(m17, i18) + 1e-4f);
            o[fo + 10] = tI.x - tM.x;
            o[fo + 11] = distE(tT, m5);
        }

        // ---- face features [24..33] (masked) ----
        const float3 w0   = loadp(fr, 0);
        const float3 w1   = loadp(fr, 21);
        const float3 nose = loadp(fr, 42);
        const float3 chin = loadp(fr, 43);
        const float3 fh   = loadp(fr, 44);
        const float3 iL   = loadp(fr, 8);    // left INDEX_TIP
        const float3 iR   = loadp(fr, 29);   // right INDEX_TIP
        o[24] = distE(w0, nose) * fg;  o[25] = distE(w0, chin) * fg;  o[26] = distE(w0, fh) * fg;
        o[27] = distE(w1, nose) * fg;  o[28] = distE(w1, chin) * fg;  o[29] = distE(w1, fh) * fg;
        o[30] = distE(iL, nose) * fg;  o[31] = distE(iL, fh) * fg;
        o[32] = distE(iR, nose) * fg;  o[33] = distE(iR, fh) * fg;

        // ---- joint angles [34..63] ----
        #pragma unroll
        for (int h = 0; h < 2; ++h) {
            const int b = h * 21;
            #pragma unroll
            for (int k = 0; k < 15; ++k) {
                float3 vp = loadp(fr, b + cP[k]);
                float3 vj = loadp(fr, b + cJ[k]);
                float3 vc = loadp(fr, b + cC[k]);
                float3 v1 = f3sub(vp, vj), v2 = f3sub(vc, vj);
                float den = sqrtf(f3dot(v1, v1) * f3dot(v2, v2)) + 1e-6f;
                o[34 + h * 15 + k] = acosc(f3dot(v1, v2) / den);
            }
        }

        // ---- palm normals [64..69] and n.up/n.fwd [76..79] ----
        #pragma unroll
        for (int h = 0; h < 2; ++h) {
            const int b = h * 21;
            float3 w = loadp(fr, b);
            float3 a = f3sub(loadp(fr, b + 5),  w);
            float3 c = f3sub(loadp(fr, b + 17), w);
            float3 n = f3cross(a, c);
            float inv = 1.0f / (f3norm(n) + 1e-6f);
            n = f3scale(n, inv);
            o[64 + h * 3 + 0] = n.x;
            o[64 + h * 3 + 1] = n.y;
            o[64 + h * 3 + 2] = n.z;
            o[76 + h * 2 + 0] = n.y;   // n . up
            o[76 + h * 2 + 1] = n.z;   // n . fwd
        }

        // ---- finger spread angles [70..75] ----
        #pragma unroll
        for (int h = 0; h < 2; ++h) {
            const int b = h * 21;
            float3 w  = loadp(fr, b);
            float3 v5  = f3sub(loadp(fr, b + 5),  w);
            float3 v9  = f3sub(loadp(fr, b + 9),  w);
            float3 v13 = f3sub(loadp(fr, b + 13), w);
            float3 v17 = f3sub(loadp(fr, b + 17), w);
            o[70 + h * 3 + 0] = acosc(f3dot(v5,  v9 ) / (sqrtf(f3dot(v5,  v5 ) * f3dot(v9,  v9 )) + 1e-6f));
            o[70 + h * 3 + 1] = acosc(f3dot(v9,  v13) / (sqrtf(f3dot(v9,  v9 ) * f3dot(v13, v13)) + 1e-6f));
            o[70 + h * 3 + 2] = acosc(f3dot(v13, v17) / (sqrtf(f3dot(v13, v13) * f3dot(v17, v17)) + 1e-6f));
        }

        // ---- temporal features ----
        const int bi = bt / TT;
        const int t  = bt - bi * TT;
        const float* xb = xyz + (size_t)bi * TT * (NLM * 3);

        float3 v0 = velAt(xb, t, 0);
        float3 v1 = velAt(xb, t, 21);
        float n0 = f3norm(v0);
        float n1 = f3norm(v1);

        // vel direction [80..85]  (denom = max(|v|,1e-6))
        {
            float i0 = 1.0f / fmaxf(n0, 1e-6f);
            float i1 = 1.0f / fmaxf(n1, 1e-6f);
            o[80] = v0.x * i0; o[81] = v0.y * i0; o[82] = v0.z * i0;
            o[83] = v1.x * i1; o[84] = v1.y * i1; o[85] = v1.z * i1;
        }

        // vel angle change [86..87]  (denom = |v|+1e-6, pad 0 at t=T-1)
        {
            float3 v0n = velAt(xb, t + 1, 0);
            float3 v1n = velAt(xb, t + 1, 21);
            float3 a0 = f3scale(v0,  1.0f / (n0 + 1e-6f));
            float3 b0 = f3scale(v0n, 1.0f / (f3norm(v0n) + 1e-6f));
            float3 a1 = f3scale(v1,  1.0f / (n1 + 1e-6f));
            float3 b1 = f3scale(v1n, 1.0f / (f3norm(v1n) + 1e-6f));
            o[86] = (t == TT - 1) ? 0.0f : acosc(f3dot(a0, b0));
            o[87] = (t == TT - 1) ? 0.0f : acosc(f3dot(a1, b1));
            // ld . rd [97]
            o[97] = f3dot(a0, a1);
        }

        // inter-hand [88..90]
        o[88] = distE(w0, w1);
        {
            float3 rel = f3sub(w1, w0);
            float ri = 1.0f / (f3norm(rel) + 1e-6f);
            o[89] = rel.x * ri;
            o[90] = rel.y * ri;
        }

        // cdiff of wrist-to-nose distance [91..92] (plain norm)
        {
            int td = t < 1 ? 1 : (t > TT - 2 ? TT - 2 : t);
            #pragma unroll
            for (int h = 0; h < 2; ++h) {
                int lm = h * 21;
                float dp = f3norm(f3sub(lpt(xb, td + 1, lm), lpt(xb, td + 1, 42)));
                float dm = f3norm(f3sub(lpt(xb, td - 1, lm), lpt(xb, td - 1, 42)));
                o[91 + h] = 0.5f * (dp - dm);
            }
        }

        // x-coordinate diffs [93..96]
        o[93] = __ldg(fr + 8  * 3) - __ldg(fr + 12 * 3);
        o[94] = __ldg(fr + 12 * 3) - __ldg(fr + 16 * 3);
        o[95] = __ldg(fr + 29 * 3) - __ldg(fr + 33 * 3);
        o[96] = __ldg(fr + 33 * 3) - __ldg(fr + 37 * 3);

        // speed [98..99]
        o[98] = n0;
        o[99] = n1;

        // accel norm [100..101]
        {
            int tc = t < 1 ? 1 : (t > TT - 2 ? TT - 2 : t);
            #pragma unroll
            for (int h = 0; h < 2; ++h) {
                int lm = h * 21;
                float3 ap = velAt(xb, tc + 1, lm);
                float3 am = velAt(xb, tc - 1, lm);
                float3 ac = make_float3(0.5f * (ap.x - am.x), 0.5f * (ap.y - am.y), 0.5f * (ap.z - am.z));
                o[100 + h] = f3norm(ac);
            }
        }

        // hand proximity sigmoid [102] (plain norm)
        {
            float hd = f3norm(f3sub(w0, w1));
            float xs = 0.25f - 5.0f * hd;
            o[102] = 1.0f / (1.0f + expf(-xs));
        }

        // body features [103..113] (masked)
        {
            float3 lsh = loadp(fr, 45), rsh = loadp(fr, 46);
            float3 lel = loadp(fr, 47), rl  = loadp(fr, 48);
            float shmx = 0.5f * (lsh.x + rsh.x);
            float shmy = 0.5f * (lsh.y + rsh.y);
            float shw  = distE(lsh, rsh);
            float si   = 1.0f / (shw + 1e-6f);
            o[103] = (w0.y - shmy) * si * bg;
            o[104] = (w0.x - shmx) * si * bg;
            o[105] = distE(w0, lsh) * bg;
            o[106] = distE(w0, lel) * bg;
            o[107] = (w1.y - shmy) * si * bg;
            o[108] = (w1.x - shmx) * si * bg;
            o[109] = distE(w1, rsh) * bg;
            o[110] = distE(w1, rl)  * bg;
            o[111] = shw * bg;
            float3 mo = f3scale(f3add(loadp(fr, 49), loadp(fr, 50)), 0.5f);
            o[112] = distE(w0, mo) * bg;
            o[113] = distE(w1, mo) * bg;
        }
    }

    __syncthreads();

    // ---- coalesced writeback: smem [frame][feat] (stride 115) -> gmem (B,T,114) ----
    const int base_frame = blockIdx.x * BLK;
    int nvalid = BT - base_frame;
    if (nvalid > BLK) nvalid = BLK;
    if (nvalid <= 0) return;
    const size_t obase = (size_t)base_frame * FPF;
    const int total = nvalid * FPF;
    for (int i = tid; i < total; i += BLK) {
        // smem index = frame*115 + feat = i + i/114
        out[obase + i] = so[i + i / FPF];
    }
}

extern "C" void kernel_launch(void* const* d_in, const int* in_sizes, int n_in,
                              void* d_out, int out_size)
{
    const float* xyz = (const float*)d_in[0];
    const float* fm  = (const float*)d_in[1];
    const float* bm  = (const float*)d_in[2];
    float* out = (float*)d_out;

    const int BT = in_sizes[1];           // face_mask element count = B*T
    const int blocks = (BT + BLK - 1) / BLK;
    geo_kernel<<<blocks, BLK>>>(xyz, fm, bm, out, BT);
}

// round 2
// speedup vs baseline: 1.8829x; 1.8829x over previous
#include <cuda_runtime.h>
#include <math.h>

#define TT   512      // frames per batch
#define NLM  51       // landmarks
#define FST  153      // floats per frame (51*3)
#define FPF  114      // features per frame
#define SP   115      // padded out-stage stride (odd -> conflict-free)
#define BLK  64       // threads per block (1 frame / thread)
#define HROWS 68      // BLK + 4 halo rows

__device__ __forceinline__ float3 f3sub(float3 a, float3 b){ return make_float3(a.x-b.x, a.y-b.y, a.z-b.z); }
__device__ __forceinline__ float3 f3add(float3 a, float3 b){ return make_float3(a.x+b.x, a.y+b.y, a.z+b.z); }
__device__ __forceinline__ float3 f3scale(float3 a, float s){ return make_float3(a.x*s, a.y*s, a.z*s); }
__device__ __forceinline__ float  f3dot(float3 a, float3 b){ return a.x*b.x + a.y*b.y + a.z*b.z; }
__device__ __forceinline__ float3 f3cross(float3 a, float3 b){
    return make_float3(a.y*b.z - a.z*b.y, a.z*b.x - a.x*b.z, a.x*b.y - a.y*b.x);
}
__device__ __forceinline__ float f3norm(float3 v){ return sqrtf(f3dot(v,v)); }
__device__ __forceinline__ float distE(float3 a, float3 b){ float3 d = f3sub(a,b); return sqrtf(f3dot(d,d) + 1e-6f); }
__device__ __forceinline__ float acosc(float c){ return acosf(fminf(fmaxf(c, -1.0f + 1e-6f), 1.0f - 1e-6f)); }

// read landmark lm of this thread's frame from smem stage
__device__ __forceinline__ float3 sp(const float* __restrict__ sF, int lm){
    return make_float3(sF[lm*3], sF[lm*3+1], sF[lm*3+2]);
}
// halo read: lmsel 0->wrist0, 1->wrist21, 2->nose(42); tau must be in [0,TT-1]
__device__ __forceinline__ float3 hp(const float* __restrict__ sH, int t0, int tau, int lmsel){
    const float* q = sH + (tau - t0 + 2) * 9 + lmsel * 3;
    return make_float3(q[0], q[1], q[2]);
}
// edge-replicated central difference velocity from halo
__device__ __forceinline__ float3 velH(const float* __restrict__ sH, int t0, int t, int lmsel){
    int tc = t < 1 ? 1 : (t > TT - 2 ? TT - 2 : t);
    float3 a = hp(sH, t0, tc + 1, lmsel);
    float3 c = hp(sH, t0, tc - 1, lmsel);
    return make_float3(0.5f*(a.x-c.x), 0.5f*(a.y-c.y), 0.5f*(a.z-c.z));
}

__constant__ int cP[15] = {0,1,2, 0,5,6, 0,9,10, 0,13,14, 0,17,18};
__constant__ int cJ[15] = {1,2,3, 5,6,7, 9,10,11, 13,14,15, 17,18,19};
__constant__ int cC[15] = {2,3,4, 6,7,8, 10,11,12, 14,15,16, 18,19,20};

extern __shared__ float smem_raw[];

__global__ void __launch_bounds__(BLK)
geo_kernel(const float* __restrict__ xyz,
           const float* __restrict__ fmask,
           const float* __restrict__ bmask,
           float* __restrict__ out,
           int BT)
{
    float* sIn   = smem_raw;                    // BLK*153 floats
    float* sHalo = sIn + BLK * FST;             // 68*9 floats
    float* sOut  = sHalo + HROWS * 9;           // BLK*115 floats

    const int tid = threadIdx.x;
    const int f0  = blockIdx.x * BLK;
    const int bt  = f0 + tid;

    // batch/time decomposition (BLK divides TT, so block is within one batch)
    const int bi = f0 / TT;
    const int t0 = f0 - bi * TT;

    // ---- stage input frames: fully coalesced float4 copy ----
    {
        const float4* gsrc = (const float4*)(xyz + (size_t)f0 * FST);
        float4* sdst = (float4*)sIn;
        #pragma unroll
        for (int i = tid; i < (BLK * FST) / 4; i += BLK) sdst[i] = gsrc[i];
    }
    // ---- stage temporal halo (landmarks 0, 21, 42 at t0-2 .. t0+65, clamped) ----
    {
        const float* xb = xyz + (size_t)bi * TT * FST;
        for (int i = tid; i < HROWS * 9; i += BLK) {
            int row = i / 9, c = i - row * 9;
            int lmsel = c / 3;
            int lm = (lmsel == 0) ? 0 : (lmsel == 1 ? 21 : 42);
            int tl = t0 - 2 + row;
            tl = tl < 0 ? 0 : (tl > TT - 1 ? TT - 1 : tl);
            sHalo[i] = __ldg(xb + (size_t)tl * FST + lm * 3 + (c - lmsel * 3));
        }
    }
    __syncthreads();

    if (bt < BT) {
        const float* fr = sIn + tid * FST;
        float* o = sOut + tid * SP;
        const float fg = __ldg(fmask + bt);
        const float bg = __ldg(bmask + bt);
        const int t = t0 + tid;    // time within batch

        // ---- per-hand: tips(5) + curls(5) + cross + d_ti  [0..23] ----
        #pragma unroll
        for (int h = 0; h < 2; ++h) {
            const int b = h * 21, fo = h * 12;
            float3 tT = sp(fr, b + 4),  tI = sp(fr, b + 8),  tM = sp(fr, b + 12);
            float3 tR = sp(fr, b + 16), tP = sp(fr, b + 20);
            o[fo + 0] = distE(tT, tI);
            o[fo + 1] = distE(tI, tM);
            o[fo + 2] = distE(tM, tR);
            o[fo + 3] = distE(tR, tP);
            o[fo + 4] = distE(tT, tP);
            float3 m2  = sp(fr, b + 2),  m5  = sp(fr, b + 5),  m9  = sp(fr, b + 9);
            float3 m13 = sp(fr, b + 13), m17 = sp(fr, b + 17);
            float3 i3  = sp(fr, b + 3),  i6  = sp(fr, b + 6),  i10 = sp(fr, b + 10);
            float3 i14 = sp(fr, b + 14), i18 = sp(fr, b + 18);
            o[fo + 5] = distE(m2,  tT) / (distE(m2,  i3)  + 1e-4f);
            o[fo + 6] = distE(m5,  tI) / (distE(m5,  i6)  + 1e-4f);
            o[fo + 7] = distE(m9,  tM) / (distE(m9,  i10) + 1e-4f);
            o[fo + 8] = distE(m13, tR) / (distE(m13, i14) + 1e-4f);
            o[fo + 9] = distE(m17, tP) / (distE(m17, i18) + 1e-4f);
            o[fo + 10] = tI.x - tM.x;
            o[fo + 11] = distE(tT, m5);
        }

        // ---- face features [24..33] (masked) ----
        const float3 w0   = sp(fr, 0);
        const float3 w1   = sp(fr, 21);
        const float3 nose = sp(fr, 42);
        const float3 chin = sp(fr, 43);
        const float3 fh   = sp(fr, 44);
        const float3 iL   = sp(fr, 8);
        const float3 iR   = sp(fr, 29);
        o[24] = distE(w0, nose) * fg;  o[25] = distE(w0, chin) * fg;  o[26] = distE(w0, fh) * fg;
        o[27] = distE(w1, nose) * fg;  o[28] = distE(w1, chin) * fg;  o[29] = distE(w1, fh) * fg;
        o[30] = distE(iL, nose) * fg;  o[31] = distE(iL, fh) * fg;
        o[32] = distE(iR, nose) * fg;  o[33] = distE(iR, fh) * fg;

        // ---- joint angles [34..63] ----
        #pragma unroll
        for (int h = 0; h < 2; ++h) {
            const int b = h * 21;
            #pragma unroll
            for (int k = 0; k < 15; ++k) {
                float3 vp = sp(fr, b + cP[k]);
                float3 vj = sp(fr, b + cJ[k]);
                float3 vc = sp(fr, b + cC[k]);
                float3 v1 = f3sub(vp, vj), v2 = f3sub(vc, vj);
                float den = sqrtf(f3dot(v1, v1) * f3dot(v2, v2)) + 1e-6f;
                o[34 + h * 15 + k] = acosc(f3dot(v1, v2) / den);
            }
        }

        // ---- palm normals [64..69] and n.up/n.fwd [76..79] ----
        #pragma unroll
        for (int h = 0; h < 2; ++h) {
            const int b = h * 21;
            float3 w = sp(fr, b);
            float3 a = f3sub(sp(fr, b + 5),  w);
            float3 c = f3sub(sp(fr, b + 17), w);
            float3 n = f3cross(a, c);
            float inv = 1.0f / (f3norm(n) + 1e-6f);
            n = f3scale(n, inv);
            o[64 + h * 3 + 0] = n.x;
            o[64 + h * 3 + 1] = n.y;
            o[64 + h * 3 + 2] = n.z;
            o[76 + h * 2 + 0] = n.y;
            o[76 + h * 2 + 1] = n.z;
        }

        // ---- finger spread angles [70..75] ----
        #pragma unroll
        for (int h = 0; h < 2; ++h) {
            const int b = h * 21;
            float3 w  = sp(fr, b);
            float3 v5  = f3sub(sp(fr, b + 5),  w);
            float3 v9  = f3sub(sp(fr, b + 9),  w);
            float3 v13 = f3sub(sp(fr, b + 13), w);
            float3 v17 = f3sub(sp(fr, b + 17), w);
            o[70 + h * 3 + 0] = acosc(f3dot(v5,  v9 ) / (sqrtf(f3dot(v5,  v5 ) * f3dot(v9,  v9 )) + 1e-6f));
            o[70 + h * 3 + 1] = acosc(f3dot(v9,  v13) / (sqrtf(f3dot(v9,  v9 ) * f3dot(v13, v13)) + 1e-6f));
            o[70 + h * 3 + 2] = acosc(f3dot(v13, v17) / (sqrtf(f3dot(v13, v13) * f3dot(v17, v17)) + 1e-6f));
        }

        // ---- temporal features (all from halo smem) ----
        float3 v0 = velH(sHalo, t0, t, 0);
        float3 v1 = velH(sHalo, t0, t, 1);
        float n0 = f3norm(v0);
        float n1 = f3norm(v1);

        // vel direction [80..85]
        {
            float i0 = 1.0f / fmaxf(n0, 1e-6f);
            float i1 = 1.0f / fmaxf(n1, 1e-6f);
            o[80] = v0.x * i0; o[81] = v0.y * i0; o[82] = v0.z * i0;
            o[83] = v1.x * i1; o[84] = v1.y * i1; o[85] = v1.z * i1;
        }

        // vel angle change [86..87] + ld.rd [97]
        {
            float3 v0n = velH(sHalo, t0, t + 1, 0);
            float3 v1n = velH(sHalo, t0, t + 1, 1);
            float3 a0 = f3scale(v0,  1.0f / (n0 + 1e-6f));
            float3 b0 = f3scale(v0n, 1.0f / (f3norm(v0n) + 1e-6f));
            float3 a1 = f3scale(v1,  1.0f / (n1 + 1e-6f));
            float3 b1 = f3scale(v1n, 1.0f / (f3norm(v1n) + 1e-6f));
            o[86] = (t == TT - 1) ? 0.0f : acosc(f3dot(a0, b0));
            o[87] = (t == TT - 1) ? 0.0f : acosc(f3dot(a1, b1));
            o[97] = f3dot(a0, a1);
        }

        // inter-hand [88..90]
        o[88] = distE(w0, w1);
        {
            float3 rel = f3sub(w1, w0);
            float ri = 1.0f / (f3norm(rel) + 1e-6f);
            o[89] = rel.x * ri;
            o[90] = rel.y * ri;
        }

        // cdiff of wrist-to-nose distance [91..92]
        {
            int td = t < 1 ? 1 : (t > TT - 2 ? TT - 2 : t);
            #pragma unroll
            for (int h = 0; h < 2; ++h) {
                float dp = f3norm(f3sub(hp(sHalo, t0, td + 1, h), hp(sHalo, t0, td + 1, 2)));
                float dm = f3norm(f3sub(hp(sHalo, t0, td - 1, h), hp(sHalo, t0, td - 1, 2)));
                o[91 + h] = 0.5f * (dp - dm);
            }
        }

        // x-coordinate diffs [93..96]
        o[93] = fr[8  * 3] - fr[12 * 3];
        o[94] = fr[12 * 3] - fr[16 * 3];
        o[95] = fr[29 * 3] - fr[33 * 3];
        o[96] = fr[33 * 3] - fr[37 * 3];

        // speed [98..99]
        o[98] = n0;
        o[99] = n1;

        // accel norm [100..101]
        {
            int tc = t < 1 ? 1 : (t > TT - 2 ? TT - 2 : t);
            #pragma unroll
            for (int h = 0; h < 2; ++h) {
                float3 ap = velH(sHalo, t0, tc + 1, h);
                float3 am = velH(sHalo, t0, tc - 1, h);
                float3 ac = make_float3(0.5f*(ap.x-am.x), 0.5f*(ap.y-am.y), 0.5f*(ap.z-am.z));
                o[100 + h] = f3norm(ac);
            }
        }

        // hand proximity sigmoid [102]
        {
            float hd = f3norm(f3sub(w0, w1));
            float xs = 0.25f - 5.0f * hd;
            o[102] = 1.0f / (1.0f + expf(-xs));
        }

        // body features [103..113] (masked)
        {
            float3 lsh = sp(fr, 45), rsh = sp(fr, 46);
            float3 lel = sp(fr, 47), rl  = sp(fr, 48);
            float shmx = 0.5f * (lsh.x + rsh.x);
            float shmy = 0.5f * (lsh.y + rsh.y);
            float shw  = distE(lsh, rsh);
            float si   = 1.0f / (shw + 1e-6f);
            o[103] = (w0.y - shmy) * si * bg;
            o[104] = (w0.x - shmx) * si * bg;
            o[105] = distE(w0, lsh) * bg;
            o[106] = distE(w0, lel) * bg;
            o[107] = (w1.y - shmy) * si * bg;
            o[108] = (w1.x - shmx) * si * bg;
            o[109] = distE(w1, rsh) * bg;
            o[110] = distE(w1, rl)  * bg;
            o[111] = shw * bg;
            float3 mo = f3scale(f3add(sp(fr, 49), sp(fr, 50)), 0.5f);
            o[112] = distE(w0, mo) * bg;
            o[113] = distE(w1, mo) * bg;
        }
    }

    __syncthreads();

    // ---- coalesced writeback ----
    int nvalid = BT - f0;
    if (nvalid > BLK) nvalid = BLK;
    if (nvalid <= 0) return;
    const size_t obase = (size_t)f0 * FPF;
    const int total = nvalid * FPF;
    for (int i = tid; i < total; i += BLK) {
        out[obase + i] = sOut[i + i / FPF];   // smem idx = frame*115 + feat
    }
}

extern "C" void kernel_launch(void* const* d_in, const int* in_sizes, int n_in,
                              void* d_out, int out_size)
{
    const float* xyz = (const float*)d_in[0];
    const float* fm  = (const float*)d_in[1];
    const float* bm  = (const float*)d_in[2];
    float* out = (float*)d_out;

    const int BT = in_sizes[1];
    const int blocks = (BT + BLK - 1) / BLK;

    const int smem_bytes = (BLK * FST + HROWS * 9 + BLK * SP) * (int)sizeof(float);
    static bool attr_set = false;
    // idempotent, safe to call every launch (not a stream op)
    cudaFuncSetAttribute(geo_kernel, cudaFuncAttributeMaxDynamicSharedMemorySize, smem_bytes);
    (void)attr_set;

    geo_kernel<<<blocks, BLK, smem_bytes>>>(xyz, fm, bm, out, BT);
}

// round 3
// speedup vs baseline: 3.8835x; 2.0625x over previous
#include <cuda_runtime.h>
#include <math.h>

#define TT   512      // frames per batch
#define NLM  51       // landmarks
#define FST  153      // floats per frame (51*3)
#define FPF  114      // features per frame
#define SP   115      // padded out-stage stride (odd -> conflict-free)
#define NF   64       // frames per block
#define BLK  128      // threads per block (2 threads / frame)
#define HROWS 68      // NF + 4 halo rows

__device__ __forceinline__ float3 f3sub(float3 a, float3 b){ return make_float3(a.x-b.x, a.y-b.y, a.z-b.z); }
__device__ __forceinline__ float3 f3add(float3 a, float3 b){ return make_float3(a.x+b.x, a.y+b.y, a.z+b.z); }
__device__ __forceinline__ float3 f3scale(float3 a, float s){ return make_float3(a.x*s, a.y*s, a.z*s); }
__device__ __forceinline__ float  f3dot(float3 a, float3 b){ return a.x*b.x + a.y*b.y + a.z*b.z; }
__device__ __forceinline__ float3 f3cross(float3 a, float3 b){
    return make_float3(a.y*b.z - a.z*b.y, a.z*b.x - a.x*b.z, a.x*b.y - a.y*b.x);
}
__device__ __forceinline__ float f3norm(float3 v){ return sqrtf(f3dot(v,v)); }
__device__ __forceinline__ float distE(float3 a, float3 b){ float3 d = f3sub(a,b); return sqrtf(f3dot(d,d) + 1e-6f); }
__device__ __forceinline__ float acosc(float c){ return acosf(fminf(fmaxf(c, -1.0f + 1e-6f), 1.0f - 1e-6f)); }
__device__ __forceinline__ float fdiv(float a, float b){ return __fdividef(a, b); }

__device__ __forceinline__ float3 sp(const float* __restrict__ sF, int lm){
    return make_float3(sF[lm*3], sF[lm*3+1], sF[lm*3+2]);
}
// halo read: lmsel 0->wrist0, 1->wrist21, 2->nose(42); tau in [0,TT-1]
__device__ __forceinline__ float3 hp(const float* __restrict__ sH, int t0, int tau, int lmsel){
    const float* q = sH + (tau - t0 + 2) * 9 + lmsel * 3;
    return make_float3(q[0], q[1], q[2]);
}
__device__ __forceinline__ float3 velH(const float* __restrict__ sH, int t0, int t, int lmsel){
    int tc = t < 1 ? 1 : (t > TT - 2 ? TT - 2 : t);
    float3 a = hp(sH, t0, tc + 1, lmsel);
    float3 c = hp(sH, t0, tc - 1, lmsel);
    return make_float3(0.5f*(a.x-c.x), 0.5f*(a.y-c.y), 0.5f*(a.z-c.z));
}

__constant__ int cP[15] = {0,1,2, 0,5,6, 0,9,10, 0,13,14, 0,17,18};
__constant__ int cJ[15] = {1,2,3, 5,6,7, 9,10,11, 13,14,15, 17,18,19};
__constant__ int cC[15] = {2,3,4, 6,7,8, 10,11,12, 14,15,16, 18,19,20};

extern __shared__ float smem_raw[];

__global__ void __launch_bounds__(BLK)
geo_kernel(const float* __restrict__ xyz,
           const float* __restrict__ fmask,
           const float* __restrict__ bmask,
           float* __restrict__ out,
           int BT)
{
    float* sIn   = smem_raw;                 // NF*153
    float* sHalo = sIn + NF * FST;           // 68*9
    float* sOut  = sHalo + HROWS * 9;        // NF*115

    const int tid = threadIdx.x;
    const int f   = tid & (NF - 1);          // frame within block
    const int sub = tid >> 6;                // 0 or 1 (whole warps)
    const int f0  = blockIdx.x * NF;
    const int bt  = f0 + f;

    const int bi = f0 / TT;
    const int t0 = f0 - bi * TT;

    // ---- stage input frames (coalesced float4, 128 threads) ----
    {
        const float4* gsrc = (const float4*)(xyz + (size_t)f0 * FST);
        float4* sdst = (float4*)sIn;
        #pragma unroll
        for (int i = tid; i < (NF * FST) / 4; i += BLK) sdst[i] = gsrc[i];
    }
    // ---- stage temporal halo ----
    {
        const float* xb = xyz + (size_t)bi * TT * FST;
        for (int i = tid; i < HROWS * 9; i += BLK) {
            int row = i / 9, c = i - row * 9;
            int lmsel = c / 3;
            int lm = (lmsel == 0) ? 0 : (lmsel == 1 ? 21 : 42);
            int tl = t0 - 2 + row;
            tl = tl < 0 ? 0 : (tl > TT - 1 ? TT - 1 : tl);
            sHalo[i] = __ldg(xb + (size_t)tl * FST + lm * 3 + (c - lmsel * 3));
        }
    }
    __syncthreads();

    if (bt < BT) {
        const float* fr = sIn + f * FST;
        float* o = sOut + f * SP;
        const float bg = __ldg(bmask + bt);
        const int t = t0 + f;
        const int h = sub;                   // each sub-thread owns one hand
        const int b = h * 21;

        // ---- per-hand: tips/curls/cross/d_ti  [h*12 .. h*12+11] ----
        {
            const int fo = h * 12;
            float3 tT = sp(fr, b + 4),  tI = sp(fr, b + 8),  tM = sp(fr, b + 12);
            float3 tR = sp(fr, b + 16), tP = sp(fr, b + 20);
            o[fo + 0] = distE(tT, tI);
            o[fo + 1] = distE(tI, tM);
            o[fo + 2] = distE(tM, tR);
            o[fo + 3] = distE(tR, tP);
            o[fo + 4] = distE(tT, tP);
            float3 m2  = sp(fr, b + 2),  m5  = sp(fr, b + 5),  m9  = sp(fr, b + 9);
            float3 m13 = sp(fr, b + 13), m17 = sp(fr, b + 17);
            float3 i3  = sp(fr, b + 3),  i6  = sp(fr, b + 6),  i10 = sp(fr, b + 10);
            float3 i14 = sp(fr, b + 14), i18 = sp(fr, b + 18);
            o[fo + 5] = fdiv(distE(m2,  tT), distE(m2,  i3)  + 1e-4f);
            o[fo + 6] = fdiv(distE(m5,  tI), distE(m5,  i6)  + 1e-4f);
            o[fo + 7] = fdiv(distE(m9,  tM), distE(m9,  i10) + 1e-4f);
            o[fo + 8] = fdiv(distE(m13, tR), distE(m13, i14) + 1e-4f);
            o[fo + 9] = fdiv(distE(m17, tP), distE(m17, i18) + 1e-4f);
            o[fo + 10] = tI.x - tM.x;
            o[fo + 11] = distE(tT, m5);
        }

        const float3 w0   = sp(fr, 0);
        const float3 w1   = sp(fr, 21);
        const float3 nose = sp(fr, 42);

        // ---- joint angles [34 + h*15 .. +14] ----
        #pragma unroll
        for (int k = 0; k < 15; ++k) {
            float3 vp = sp(fr, b + cP[k]);
            float3 vj = sp(fr, b + cJ[k]);
            float3 vc = sp(fr, b + cC[k]);
            float3 v1 = f3sub(vp, vj), v2 = f3sub(vc, vj);
            float den = sqrtf(f3dot(v1, v1) * f3dot(v2, v2)) + 1e-6f;
            o[34 + h * 15 + k] = acosc(fdiv(f3dot(v1, v2), den));
        }

        // ---- palm normal [64+h*3..], n.up/n.fwd [76+h*2..] ----
        {
            float3 w = (h == 0) ? w0 : w1;
            float3 a = f3sub(sp(fr, b + 5),  w);
            float3 c = f3sub(sp(fr, b + 17), w);
            float3 n = f3cross(a, c);
            float inv = fdiv(1.0f, f3norm(n) + 1e-6f);
            n = f3scale(n, inv);
            o[64 + h * 3 + 0] = n.x;
            o[64 + h * 3 + 1] = n.y;
            o[64 + h * 3 + 2] = n.z;
            o[76 + h * 2 + 0] = n.y;
            o[76 + h * 2 + 1] = n.z;
        }

        // ---- finger spread [70+h*3..] ----
        {
            float3 w = (h == 0) ? w0 : w1;
            float3 v5  = f3sub(sp(fr, b + 5),  w);
            float3 v9  = f3sub(sp(fr, b + 9),  w);
            float3 v13 = f3sub(sp(fr, b + 13), w);
            float3 v17 = f3sub(sp(fr, b + 17), w);
            o[70 + h * 3 + 0] = acosc(fdiv(f3dot(v5,  v9 ), sqrtf(f3dot(v5,  v5 ) * f3dot(v9,  v9 )) + 1e-6f));
            o[70 + h * 3 + 1] = acosc(fdiv(f3dot(v9,  v13), sqrtf(f3dot(v9,  v9 ) * f3dot(v13, v13)) + 1e-6f));
            o[70 + h * 3 + 2] = acosc(fdiv(f3dot(v13, v17), sqrtf(f3dot(v13, v13) * f3dot(v17, v17)) + 1e-6f));
        }

        // ---- temporal for this hand ----
        float3 vh = velH(sHalo, t0, t, h);
        float nh = f3norm(vh);
        {
            float ih = fdiv(1.0f, fmaxf(nh, 1e-6f));
            o[80 + h * 3 + 0] = vh.x * ih;
            o[80 + h * 3 + 1] = vh.y * ih;
            o[80 + h * 3 + 2] = vh.z * ih;
        }
        {
            float3 vhn = velH(sHalo, t0, t + 1, h);
            float3 a = f3scale(vh,  fdiv(1.0f, nh + 1e-6f));
            float3 bb = f3scale(vhn, fdiv(1.0f, f3norm(vhn) + 1e-6f));
            o[86 + h] = (t == TT - 1) ? 0.0f : acosc(f3dot(a, bb));
        }
        // cdiff wrist-nose distance [91+h]
        {
            int td = t < 1 ? 1 : (t > TT - 2 ? TT - 2 : t);
            float dp = f3norm(f3sub(hp(sHalo, t0, td + 1, h), hp(sHalo, t0, td + 1, 2)));
            float dm = f3norm(f3sub(hp(sHalo, t0, td - 1, h), hp(sHalo, t0, td - 1, 2)));
            o[91 + h] = 0.5f * (dp - dm);
        }
        // x diffs [93+h*2, 94+h*2]
        o[93 + h * 2] = fr[(b + 8)  * 3] - fr[(b + 12) * 3];
        o[94 + h * 2] = fr[(b + 12) * 3] - fr[(b + 16) * 3];
        // speed [98+h]
        o[98 + h] = nh;
        // accel norm [100+h]
        {
            int tc = t < 1 ? 1 : (t > TT - 2 ? TT - 2 : t);
            float3 ap = velH(sHalo, t0, tc + 1, h);
            float3 am = velH(sHalo, t0, tc - 1, h);
            float3 ac = make_float3(0.5f*(ap.x-am.x), 0.5f*(ap.y-am.y), 0.5f*(ap.z-am.z));
            o[100 + h] = f3norm(ac);
        }

        if (sub == 0) {
            const float fg = __ldg(fmask + bt);
            const float3 chin = sp(fr, 43);
            const float3 fh   = sp(fr, 44);
            const float3 iL   = sp(fr, 8);
            const float3 iR   = sp(fr, 29);
            o[24] = distE(w0, nose) * fg;  o[25] = distE(w0, chin) * fg;  o[26] = distE(w0, fh) * fg;
            o[27] = distE(w1, nose) * fg;  o[28] = distE(w1, chin) * fg;  o[29] = distE(w1, fh) * fg;
            o[30] = distE(iL, nose) * fg;  o[31] = distE(iL, fh) * fg;
            o[32] = distE(iR, nose) * fg;  o[33] = distE(iR, fh) * fg;

            // inter-hand [88..90]
            o[88] = distE(w0, w1);
            {
                float3 rel = f3sub(w1, w0);
                float ri = fdiv(1.0f, f3norm(rel) + 1e-6f);
                o[89] = rel.x * ri;
                o[90] = rel.y * ri;
            }
            // hand proximity sigmoid [102]
            {
                float hd = f3norm(f3sub(w0, w1));
                float xs = 0.25f - 5.0f * hd;
                o[102] = fdiv(1.0f, 1.0f + __expf(-xs));
            }
            // body for left hand + shared [103..106, 111, 112]
            {
                float3 lsh = sp(fr, 45), rsh = sp(fr, 46);
                float3 lel = sp(fr, 47);
                float shmx = 0.5f * (lsh.x + rsh.x);
                float shmy = 0.5f * (lsh.y + rsh.y);
                float shw  = distE(lsh, rsh);
                float si   = fdiv(1.0f, shw + 1e-6f);
                o[103] = (w0.y - shmy) * si * bg;
                o[104] = (w0.x - shmx) * si * bg;
                o[105] = distE(w0, lsh) * bg;
                o[106] = distE(w0, lel) * bg;
                o[111] = shw * bg;
                float3 mo = f3scale(f3add(sp(fr, 49), sp(fr, 50)), 0.5f);
                o[112] = distE(w0, mo) * bg;
            }
        } else {
            // ld . rd [97]  (needs both hands' normalized velocities)
            {
                float3 v0 = velH(sHalo, t0, t, 0);
                float3 a0 = f3scale(v0, fdiv(1.0f, f3norm(v0) + 1e-6f));
                float3 a1 = f3scale(vh, fdiv(1.0f, nh + 1e-6f));
                o[97] = f3dot(a0, a1);
            }
            // body for right hand [107..110, 113]
            {
                float3 lsh = sp(fr, 45), rsh = sp(fr, 46);
                float3 rel = sp(fr, 48);
                float shmx = 0.5f * (lsh.x + rsh.x);
                float shmy = 0.5f * (lsh.y + rsh.y);
                float shw  = distE(lsh, rsh);
                float si   = fdiv(1.0f, shw + 1e-6f);
                o[107] = (w1.y - shmy) * si * bg;
                o[108] = (w1.x - shmx) * si * bg;
                o[109] = distE(w1, rsh) * bg;
                o[110] = distE(w1, rel) * bg;
                float3 mo = f3scale(f3add(sp(fr, 49), sp(fr, 50)), 0.5f);
                o[113] = distE(w1, mo) * bg;
            }
        }
    }

    __syncthreads();

    // ---- coalesced writeback (128 threads) ----
    int nvalid = BT - f0;
    if (nvalid > NF) nvalid = NF;
    if (nvalid <= 0) return;
    const size_t obase = (size_t)f0 * FPF;
    const int total = nvalid * FPF;
    for (int i = tid; i < total; i += BLK) {
        out[obase + i] = sOut[i + i / FPF];
    }
}

extern "C" void kernel_launch(void* const* d_in, const int* in_sizes, int n_in,
                              void* d_out, int out_size)
{
    const float* xyz = (const float*)d_in[0];
    const float* fm  = (const float*)d_in[1];
    const float* bm  = (const float*)d_in[2];
    float* out = (float*)d_out;

    const int BT = in_sizes[1];
    const int blocks = (BT + NF - 1) / NF;

    const int smem_bytes = (NF * FST + HROWS * 9 + NF * SP) * (int)sizeof(float);
    cudaFuncSetAttribute(geo_kernel, cudaFuncAttributeMaxDynamicSharedMemorySize, smem_bytes);

    geo_kernel<<<blocks, BLK, smem_bytes>>>(xyz, fm, bm, out, BT);
}

// round 5
// speedup vs baseline: 4.8093x; 1.2384x over previous
#include <cuda_runtime.h>
#include <math.h>

#define TT   512      // frames per batch
#define NLM  51       // landmarks
#define FST  153      // floats per frame (51*3)
#define FPF  114      // features per frame
#define SP   115      // padded out-stage stride
#define NF   64       // frames per block
#define BLK  256      // threads per block (4 threads / frame)
#define HROWS 68      // NF + 4 halo rows

__device__ __forceinline__ float3 f3sub(float3 a, float3 b){ return make_float3(a.x-b.x, a.y-b.y, a.z-b.z); }
__device__ __forceinline__ float3 f3add(float3 a, float3 b){ return make_float3(a.x+b.x, a.y+b.y, a.z+b.z); }
__device__ __forceinline__ float3 f3scale(float3 a, float s){ return make_float3(a.x*s, a.y*s, a.z*s); }
__device__ __forceinline__ float  f3dot(float3 a, float3 b){ return a.x*b.x + a.y*b.y + a.z*b.z; }
__device__ __forceinline__ float3 f3cross(float3 a, float3 b){
    return make_float3(a.y*b.z - a.z*b.y, a.z*b.x - a.x*b.z, a.x*b.y - a.y*b.x);
}
__device__ __forceinline__ float f3norm(float3 v){ return sqrtf(f3dot(v,v)); }
__device__ __forceinline__ float distE(float3 a, float3 b){ float3 d = f3sub(a,b); return sqrtf(f3dot(d,d) + 1e-6f); }
__device__ __forceinline__ float acosc(float c){ return acosf(fminf(fmaxf(c, -1.0f + 1e-6f), 1.0f - 1e-6f)); }
__device__ __forceinline__ float fdiv(float a, float b){ return __fdividef(a, b); }

__device__ __forceinline__ float3 sp(const float* __restrict__ sF, int lm){
    return make_float3(sF[lm*3], sF[lm*3+1], sF[lm*3+2]);
}
// halo read: lmsel 0->wrist0, 1->wrist21, 2->nose(42); tau in [0,TT-1]
__device__ __forceinline__ float3 hp(const float* __restrict__ sH, int t0, int tau, int lmsel){
    const float* q = sH + (tau - t0 + 2) * 9 + lmsel * 3;
    return make_float3(q[0], q[1], q[2]);
}
__device__ __forceinline__ float3 velH(const float* __restrict__ sH, int t0, int t, int lmsel){
    int tc = t < 1 ? 1 : (t > TT - 2 ? TT - 2 : t);
    float3 a = hp(sH, t0, tc + 1, lmsel);
    float3 c = hp(sH, t0, tc - 1, lmsel);
    return make_float3(0.5f*(a.x-c.x), 0.5f*(a.y-c.y), 0.5f*(a.z-c.z));
}

__constant__ int cP[15] = {0,1,2, 0,5,6, 0,9,10, 0,13,14, 0,17,18};
__constant__ int cJ[15] = {1,2,3, 5,6,7, 9,10,11, 13,14,15, 17,18,19};
__constant__ int cC[15] = {2,3,4, 6,7,8, 10,11,12, 14,15,16, 18,19,20};

extern __shared__ float smem_raw[];

__global__ void __launch_bounds__(BLK)
geo_kernel(const float* __restrict__ xyz,
           const float* __restrict__ fmask,
           const float* __restrict__ bmask,
           float* __restrict__ out,
           int BT)
{
    float* sIn   = smem_raw;                 // NF*153
    float* sHalo = sIn + NF * FST;           // 68*9
    float* sOut  = sHalo + HROWS * 9;        // NF*115

    const int tid = threadIdx.x;
    const int f   = tid & (NF - 1);          // frame within block
    const int sub = tid >> 6;                // 0..3, whole warps
    const int f0  = blockIdx.x * NF;
    const int bt  = f0 + f;

    const int bi = f0 / TT;
    const int t0 = f0 - bi * TT;

    // ---- stage input frames (coalesced float4, 256 threads) ----
    {
        const float4* gsrc = (const float4*)(xyz + (size_t)f0 * FST);
        float4* sdst = (float4*)sIn;
        #pragma unroll
        for (int i = tid; i < (NF * FST) / 4; i += BLK) sdst[i] = gsrc[i];
    }
    // ---- stage temporal halo ----
    {
        const float* xb = xyz + (size_t)bi * TT * FST;
        for (int i = tid; i < HROWS * 9; i += BLK) {
            int row = i / 9, c = i - row * 9;
            int lmsel = c / 3;
            int lm = (lmsel == 0) ? 0 : (lmsel == 1 ? 21 : 42);
            int tl = t0 - 2 + row;
            tl = tl < 0 ? 0 : (tl > TT - 1 ? TT - 1 : tl);
            sHalo[i] = __ldg(xb + (size_t)tl * FST + lm * 3 + (c - lmsel * 3));
        }
    }
    __syncthreads();

    if (bt < BT) {
        const float* fr = sIn + f * FST;
        float* o = sOut + f * SP;
        const int t = t0 + f;
        const int h    = sub >> 1;           // hand
        const int part = sub & 1;            // split within hand
        const int b  = h * 21;
        const int fo = h * 12;

        const float3 w0 = sp(fr, 0);
        const float3 w1 = sp(fr, 21);
        const float3 wH = (h == 0) ? w0 : w1;

        if (part == 0) {
            // ---- tips + cross [fo+0..4, fo+10] ----
            float3 tT = sp(fr, b + 4),  tI = sp(fr, b + 8),  tM = sp(fr, b + 12);
            float3 tR = sp(fr, b + 16), tP = sp(fr, b + 20);
            o[fo + 0] = distE(tT, tI);
            o[fo + 1] = distE(tI, tM);
            o[fo + 2] = distE(tM, tR);
            o[fo + 3] = distE(tR, tP);
            o[fo + 4] = distE(tT, tP);
            o[fo + 10] = tI.x - tM.x;

            // ---- joint angles k=0..7 ----
            #pragma unroll
            for (int k = 0; k < 8; ++k) {
                float3 vp = sp(fr, b + cP[k]);
                float3 vj = sp(fr, b + cJ[k]);
                float3 vc = sp(fr, b + cC[k]);
                float3 v1 = f3sub(vp, vj), v2 = f3sub(vc, vj);
                float den = sqrtf(f3dot(v1, v1) * f3dot(v2, v2)) + 1e-6f;
                o[34 + h * 15 + k] = acosc(fdiv(f3dot(v1, v2), den));
            }

            // ---- spread angles 0,1 ----
            {
                float3 v5  = f3sub(sp(fr, b + 5),  wH);
                float3 v9  = f3sub(sp(fr, b + 9),  wH);
                float3 v13 = f3sub(sp(fr, b + 13), wH);
                o[70 + h * 3 + 0] = acosc(fdiv(f3dot(v5, v9 ), sqrtf(f3dot(v5, v5 ) * f3dot(v9,  v9 )) + 1e-6f));
                o[70 + h * 3 + 1] = acosc(fdiv(f3dot(v9, v13), sqrtf(f3dot(v9, v9 ) * f3dot(v13, v13)) + 1e-6f));
            }

            // ---- vel direction + speed ----
            {
                float3 vh = velH(sHalo, t0, t, h);
                float nh = f3norm(vh);
                float ih = fdiv(1.0f, fmaxf(nh, 1e-6f));
                o[80 + h * 3 + 0] = vh.x * ih;
                o[80 + h * 3 + 1] = vh.y * ih;
                o[80 + h * 3 + 2] = vh.z * ih;
                o[98 + h] = nh;
            }

            // ---- x diffs ----
            o[93 + h * 2] = fr[(b + 8)  * 3] - fr[(b + 12) * 3];
            o[94 + h * 2] = fr[(b + 12) * 3] - fr[(b + 16) * 3];

            // ---- face half (masked) ----
            {
                const float fg = __ldg(fmask + bt);
                const float3 nose = sp(fr, 42);
                const float3 chin = sp(fr, 43);
                const float3 fh   = sp(fr, 44);
                const float3 tip  = (h == 0) ? sp(fr, 8) : sp(fr, 29);
                o[24 + h * 3 + 0] = distE(wH, nose) * fg;
                o[24 + h * 3 + 1] = distE(wH, chin) * fg;
                o[24 + h * 3 + 2] = distE(wH, fh)   * fg;
                o[30 + h * 2 + 0] = distE(tip, nose) * fg;
                o[30 + h * 2 + 1] = distE(tip, fh)   * fg;
            }
        } else {
            // ---- curls + d_ti [fo+5..9, fo+11] ----
            {
                float3 tT = sp(fr, b + 4),  tI = sp(fr, b + 8),  tM = sp(fr, b + 12);
                float3 tR = sp(fr, b + 16), tP = sp(fr, b + 20);
                float3 m2  = sp(fr, b + 2),  m5  = sp(fr, b + 5),  m9  = sp(fr, b + 9);
                float3 m13 = sp(fr, b + 13), m17 = sp(fr, b + 17);
                float3 i3  = sp(fr, b + 3),  i6  = sp(fr, b + 6),  i10 = sp(fr, b + 10);
                float3 i14 = sp(fr, b + 14), i18 = sp(fr, b + 18);
                o[fo + 5] = fdiv(distE(m2,  tT), distE(m2,  i3)  + 1e-4f);
                o[fo + 6] = fdiv(distE(m5,  tI), distE(m5,  i6)  + 1e-4f);
                o[fo + 7] = fdiv(distE(m9,  tM), distE(m9,  i10) + 1e-4f);
                o[fo + 8] = fdiv(distE(m13, tR), distE(m13, i14) + 1e-4f);
                o[fo + 9] = fdiv(distE(m17, tP), distE(m17, i18) + 1e-4f);
                o[fo + 11] = distE(tT, m5);
            }

            // ---- joint angles k=8..14 ----
            #pragma unroll
            for (int k = 8; k < 15; ++k) {
                float3 vp = sp(fr, b + cP[k]);
                float3 vj = sp(fr, b + cJ[k]);
                float3 vc = sp(fr, b + cC[k]);
                float3 v1 = f3sub(vp, vj), v2 = f3sub(vc, vj);
                float den = sqrtf(f3dot(v1, v1) * f3dot(v2, v2)) + 1e-6f;
                o[34 + h * 15 + k] = acosc(fdiv(f3dot(v1, v2), den));
            }

            // ---- spread angle 2 ----
            {
                float3 v13 = f3sub(sp(fr, b + 13), wH);
                float3 v17 = f3sub(sp(fr, b + 17), wH);
                o[70 + h * 3 + 2] = acosc(fdiv(f3dot(v13, v17), sqrtf(f3dot(v13, v13) * f3dot(v17, v17)) + 1e-6f));
            }

            // ---- palm normal + up/fwd ----
            {
                float3 a = f3sub(sp(fr, b + 5),  wH);
                float3 c = f3sub(sp(fr, b + 17), wH);
                float3 n = f3cross(a, c);
                float inv = fdiv(1.0f, f3norm(n) + 1e-6f);
                n = f3scale(n, inv);
                o[64 + h * 3 + 0] = n.x;
                o[64 + h * 3 + 1] = n.y;
                o[64 + h * 3 + 2] = n.z;
                o[76 + h * 2 + 0] = n.y;
                o[76 + h * 2 + 1] = n.z;
            }

            // ---- temporal: angle change, nose cdiff, accel ----
            float3 vh = velH(sHalo, t0, t, h);
            float nh = f3norm(vh);
            {
                float3 vhn = velH(sHalo, t0, t + 1, h);
                float3 a  = f3scale(vh,  fdiv(1.0f, nh + 1e-6f));
                float3 bb = f3scale(vhn, fdiv(1.0f, f3norm(vhn) + 1e-6f));
                o[86 + h] = (t == TT - 1) ? 0.0f : acosc(f3dot(a, bb));
            }
            {
                int td = t < 1 ? 1 : (t > TT - 2 ? TT - 2 : t);
                float dp = f3norm(f3sub(hp(sHalo, t0, td + 1, h), hp(sHalo, t0, td + 1, 2)));
                float dm = f3norm(f3sub(hp(sHalo, t0, td - 1, h), hp(sHalo, t0, td - 1, 2)));
                o[91 + h] = 0.5f * (dp - dm);
            }
            {
                int tc = t < 1 ? 1 : (t > TT - 2 ? TT - 2 : t);
                float3 ap = velH(sHalo, t0, tc + 1, h);
                float3 am = velH(sHalo, t0, tc - 1, h);
                float3 ac = make_float3(0.5f*(ap.x-am.x), 0.5f*(ap.y-am.y), 0.5f*(ap.z-am.z));
                o[100 + h] = f3norm(ac);
            }

            const float bg = __ldg(bmask + bt);
            if (h == 0) {
                // sub1: inter-hand + body left
                o[88] = distE(w0, w1);
                {
                    float3 rel = f3sub(w1, w0);
                    float ri = fdiv(1.0f, f3norm(rel) + 1e-6f);
                    o[89] = rel.x * ri;
                    o[90] = rel.y * ri;
                }
                {
                    float3 lsh = sp(fr, 45), rsh = sp(fr, 46);
                    float3 lel = sp(fr, 47);
                    float shmx = 0.5f * (lsh.x + rsh.x);
                    float shmy = 0.5f * (lsh.y + rsh.y);
                    float shw  = distE(lsh, rsh);
                    float si   = fdiv(1.0f, shw + 1e-6f);
                    o[103] = (w0.y - shmy) * si * bg;
                    o[104] = (w0.x - shmx) * si * bg;
                    o[105] = distE(w0, lsh) * bg;
                    o[106] = distE(w0, lel) * bg;
                    o[111] = shw * bg;
                    float3 mo = f3scale(f3add(sp(fr, 49), sp(fr, 50)), 0.5f);
                    o[112] = distE(w0, mo) * bg;
                }
            } else {
                // sub3: ld.rd + sigmoid + body right
                {
                    float3 v0 = velH(sHalo, t0, t, 0);
                    float3 a0 = f3scale(v0, fdiv(1.0f, f3norm(v0) + 1e-6f));
                    float3 a1 = f3scale(vh, fdiv(1.0f, nh + 1e-6f));
                    o[97] = f3dot(a0, a1);
                }
                {
                    float hd = f3norm(f3sub(w0, w1));
                    float xs = 0.25f - 5.0f * hd;
                    o[102] = fdiv(1.0f, 1.0f + __expf(-xs));
                }
                {
                    float3 lsh = sp(fr, 45), rsh = sp(fr, 46);
                    float3 rel = sp(fr, 48);
                    float shmx = 0.5f * (lsh.x + rsh.x);
                    float shmy = 0.5f * (lsh.y + rsh.y);
                    float shw  = distE(lsh, rsh);
                    float si   = fdiv(1.0f, shw + 1e-6f);
                    o[107] = (w1.y - shmy) * si * bg;
                    o[108] = (w1.x - shmx) * si * bg;
                    o[109] = distE(w1, rsh) * bg;
                    o[110] = distE(w1, rel) * bg;
                    float3 mo = f3scale(f3add(sp(fr, 49), sp(fr, 50)), 0.5f);
                    o[113] = distE(w1, mo) * bg;
                }
            }
        }
    }

    __syncthreads();

    // ---- coalesced writeback (256 threads) ----
    int nvalid = BT - f0;
    if (nvalid > NF) nvalid = NF;
    if (nvalid <= 0) return;
    const size_t obase = (size_t)f0 * FPF;
    const int total = nvalid * FPF;
    for (int i = tid; i < total; i += BLK) {
        out[obase + i] = sOut[i + i / FPF];
    }
}

extern "C" void kernel_launch(void* const* d_in, const int* in_sizes, int n_in,
                              void* d_out, int out_size)
{
    const float* xyz = (const float*)d_in[0];
    const float* fm  = (const float*)d_in[1];
    const float* bm  = (const float*)d_in[2];
    float* out = (float*)d_out;

    const int BT = in_sizes[1];
    const int blocks = (BT + NF - 1) / NF;

    const int smem_bytes = (NF * FST + HROWS * 9 + NF * SP) * (int)sizeof(float);
    cudaFuncSetAttribute(geo_kernel, cudaFuncAttributeMaxDynamicSharedMemorySize, smem_bytes);

    geo_kernel<<<blocks, BLK, smem_bytes>>>(xyz, fm, bm, out, BT);
}

// round 7
// speedup vs baseline: 4.8362x; 1.0056x over previous
#include <cuda_runtime.h>
#include <math.h>

#define TT   512      // frames per batch
#define NLM  51       // landmarks
#define FST  153      // floats per frame (51*3)
#define FPF  114      // features per frame
#define SP   115      // padded out-stage stride (odd -> conflict-free)
#define NF   32       // frames per block
#define BLK  256      // threads per block (8 threads / frame)
#define HROWS 36      // NF + 4 halo rows

__device__ __forceinline__ float3 f3sub(float3 a, float3 b){ return make_float3(a.x-b.x, a.y-b.y, a.z-b.z); }
__device__ __forceinline__ float3 f3add(float3 a, float3 b){ return make_float3(a.x+b.x, a.y+b.y, a.z+b.z); }
__device__ __forceinline__ float3 f3scale(float3 a, float s){ return make_float3(a.x*s, a.y*s, a.z*s); }
__device__ __forceinline__ float  f3dot(float3 a, float3 b){ return a.x*b.x + a.y*b.y + a.z*b.z; }
__device__ __forceinline__ float3 f3cross(float3 a, float3 b){
    return make_float3(a.y*b.z - a.z*b.y, a.z*b.x - a.x*b.z, a.x*b.y - a.y*b.x);
}
__device__ __forceinline__ float f3norm(float3 v){ return sqrtf(f3dot(v,v)); }
__device__ __forceinline__ float distE(float3 a, float3 b){ float3 d = f3sub(a,b); return sqrtf(f3dot(d,d) + 1e-6f); }
__device__ __forceinline__ float acosc(float c){ return acosf(fminf(fmaxf(c, -1.0f + 1e-6f), 1.0f - 1e-6f)); }
__device__ __forceinline__ float fdiv(float a, float b){ return __fdividef(a, b); }

__device__ __forceinline__ float3 sp(const float* __restrict__ sF, int lm){
    return make_float3(sF[lm*3], sF[lm*3+1], sF[lm*3+2]);
}
// halo read: lmsel 0->wrist0, 1->wrist21, 2->nose(42); tau in [0,TT-1]
__device__ __forceinline__ float3 hp(const float* __restrict__ sH, int t0, int tau, int lmsel){
    const float* q = sH + (tau - t0 + 2) * 9 + lmsel * 3;
    return make_float3(q[0], q[1], q[2]);
}
__device__ __forceinline__ float3 velH(const float* __restrict__ sH, int t0, int t, int lmsel){
    int tc = t < 1 ? 1 : (t > TT - 2 ? TT - 2 : t);
    float3 a = hp(sH, t0, tc + 1, lmsel);
    float3 c = hp(sH, t0, tc - 1, lmsel);
    return make_float3(0.5f*(a.x-c.x), 0.5f*(a.y-c.y), 0.5f*(a.z-c.z));
}

__constant__ int cP[15] = {0,1,2, 0,5,6, 0,9,10, 0,13,14, 0,17,18};
__constant__ int cJ[15] = {1,2,3, 5,6,7, 9,10,11, 13,14,15, 17,18,19};
__constant__ int cC[15] = {2,3,4, 6,7,8, 10,11,12, 14,15,16, 18,19,20};

extern __shared__ float smem_raw[];

__global__ void __launch_bounds__(BLK, 5)
geo_kernel(const float* __restrict__ xyz,
           const float* __restrict__ fmask,
           const float* __restrict__ bmask,
           float* __restrict__ out,
           int BT)
{
    float* sIn   = smem_raw;                 // NF*153
    float* sHalo = sIn + NF * FST;           // 36*9
    float* sOut  = sHalo + HROWS * 9;        // NF*115

    const int tid = threadIdx.x;
    const int f   = tid & (NF - 1);          // frame within block
    const int sub = tid >> 5;                // 0..7, whole warps
    const int f0  = blockIdx.x * NF;
    const int bt  = f0 + f;

    const int bi = f0 / TT;
    const int t0 = f0 - bi * TT;

    // ---- stage input frames (coalesced float4) ----
    {
        const float4* gsrc = (const float4*)(xyz + (size_t)f0 * FST);
        float4* sdst = (float4*)sIn;
        #pragma unroll
        for (int i = tid; i < (NF * FST) / 4; i += BLK) sdst[i] = gsrc[i];
    }
    // ---- stage temporal halo ----
    {
        const float* xb = xyz + (size_t)bi * TT * FST;
        for (int i = tid; i < HROWS * 9; i += BLK) {
            int row = i / 9, c = i - row * 9;
            int lmsel = c / 3;
            int lm = (lmsel == 0) ? 0 : (lmsel == 1 ? 21 : 42);
            int tl = t0 - 2 + row;
            tl = tl < 0 ? 0 : (tl > TT - 1 ? TT - 1 : tl);
            sHalo[i] = __ldg(xb + (size_t)tl * FST + lm * 3 + (c - lmsel * 3));
        }
    }
    __syncthreads();

    if (bt < BT) {
        const float* fr = sIn + f * FST;
        float* o = sOut + f * SP;
        const int t = t0 + f;
        const int h    = sub >> 2;           // hand
        const int part = sub & 3;            // 4-way split within hand
        const int b  = h * 21;
        const int fo = h * 12;

        const float3 w0 = sp(fr, 0);
        const float3 w1 = sp(fr, 21);
        const float3 wH = (h == 0) ? w0 : w1;

        if (part == 0) {
            // ---- tips + cross ----
            float3 tT = sp(fr, b + 4),  tI = sp(fr, b + 8),  tM = sp(fr, b + 12);
            float3 tR = sp(fr, b + 16), tP = sp(fr, b + 20);
            o[fo + 0] = distE(tT, tI);
            o[fo + 1] = distE(tI, tM);
            o[fo + 2] = distE(tM, tR);
            o[fo + 3] = distE(tR, tP);
            o[fo + 4] = distE(tT, tP);
            o[fo + 10] = tI.x - tM.x;

            // ---- joint angles k=0..4 ----
            #pragma unroll
            for (int k = 0; k < 5; ++k) {
                float3 vp = sp(fr, b + cP[k]);
                float3 vj = sp(fr, b + cJ[k]);
                float3 vc = sp(fr, b + cC[k]);
                float3 v1 = f3sub(vp, vj), v2 = f3sub(vc, vj);
                float den = sqrtf(f3dot(v1, v1) * f3dot(v2, v2)) + 1e-6f;
                o[34 + h * 15 + k] = acosc(fdiv(f3dot(v1, v2), den));
            }

            // ---- body block (masked) ----
            const float bg = __ldg(bmask + bt);
            float3 lsh = sp(fr, 45), rsh = sp(fr, 46);
            float shmx = 0.5f * (lsh.x + rsh.x);
            float shmy = 0.5f * (lsh.y + rsh.y);
            float shw  = distE(lsh, rsh);
            float si   = fdiv(1.0f, shw + 1e-6f);
            float3 mo = f3scale(f3add(sp(fr, 49), sp(fr, 50)), 0.5f);
            if (h == 0) {
                float3 lel = sp(fr, 47);
                o[103] = (w0.y - shmy) * si * bg;
                o[104] = (w0.x - shmx) * si * bg;
                o[105] = distE(w0, lsh) * bg;
                o[106] = distE(w0, lel) * bg;
                o[111] = shw * bg;
                o[112] = distE(w0, mo) * bg;
            } else {
                float3 rel = sp(fr, 48);
                o[107] = (w1.y - shmy) * si * bg;
                o[108] = (w1.x - shmx) * si * bg;
                o[109] = distE(w1, rsh) * bg;
                o[110] = distE(w1, rel) * bg;
                o[113] = distE(w1, mo) * bg;
            }
        } else if (part == 1) {
            // ---- joint angles k=5..9 ----
            #pragma unroll
            for (int k = 5; k < 10; ++k) {
                float3 vp = sp(fr, b + cP[k]);
                float3 vj = sp(fr, b + cJ[k]);
                float3 vc = sp(fr, b + cC[k]);
                float3 v1 = f3sub(vp, vj), v2 = f3sub(vc, vj);
                float den = sqrtf(f3dot(v1, v1) * f3dot(v2, v2)) + 1e-6f;
                o[34 + h * 15 + k] = acosc(fdiv(f3dot(v1, v2), den));
            }

            // ---- face half (masked) ----
            {
                const float fg = __ldg(fmask + bt);
                const float3 nose = sp(fr, 42);
                const float3 chin = sp(fr, 43);
                const float3 fh   = sp(fr, 44);
                const float3 tip  = (h == 0) ? sp(fr, 8) : sp(fr, 29);
                o[24 + h * 3 + 0] = distE(wH, nose) * fg;
                o[24 + h * 3 + 1] = distE(wH, chin) * fg;
                o[24 + h * 3 + 2] = distE(wH, fh)   * fg;
                o[30 + h * 2 + 0] = distE(tip, nose) * fg;
                o[30 + h * 2 + 1] = distE(tip, fh)   * fg;
            }

            // ---- x diffs ----
            o[93 + h * 2] = fr[(b + 8)  * 3] - fr[(b + 12) * 3];
            o[94 + h * 2] = fr[(b + 12) * 3] - fr[(b + 16) * 3];

            if (h == 0) {
                // inter-hand + sigmoid
                o[88] = distE(w0, w1);
                float3 rel = f3sub(w1, w0);
                float rnv = f3norm(rel);
                float ri = fdiv(1.0f, rnv + 1e-6f);
                o[89] = rel.x * ri;
                o[90] = rel.y * ri;
                float xs = 0.25f - 5.0f * rnv;
                o[102] = fdiv(1.0f, 1.0f + __expf(-xs));
            } else {
                // ld . rd
                float3 v0 = velH(sHalo, t0, t, 0);
                float3 v1 = velH(sHalo, t0, t, 1);
                float3 a0 = f3scale(v0, fdiv(1.0f, f3norm(v0) + 1e-6f));
                float3 a1 = f3scale(v1, fdiv(1.0f, f3norm(v1) + 1e-6f));
                o[97] = f3dot(a0, a1);
            }
        } else if (part == 2) {
            // ---- curls + d_ti ----
            {
                float3 tT = sp(fr, b + 4),  tI = sp(fr, b + 8),  tM = sp(fr, b + 12);
                float3 tR = sp(fr, b + 16), tP = sp(fr, b + 20);
                float3 m2  = sp(fr, b + 2),  m5  = sp(fr, b + 5),  m9  = sp(fr, b + 9);
                float3 m13 = sp(fr, b + 13), m17 = sp(fr, b + 17);
                float3 i3  = sp(fr, b + 3),  i6  = sp(fr, b + 6),  i10 = sp(fr, b + 10);
                float3 i14 = sp(fr, b + 14), i18 = sp(fr, b + 18);
                o[fo + 5] = fdiv(distE(m2,  tT), distE(m2,  i3)  + 1e-4f);
                o[fo + 6] = fdiv(distE(m5,  tI), distE(m5,  i6)  + 1e-4f);
                o[fo + 7] = fdiv(distE(m9,  tM), distE(m9,  i10) + 1e-4f);
                o[fo + 8] = fdiv(distE(m13, tR), distE(m13, i14) + 1e-4f);
                o[fo + 9] = fdiv(distE(m17, tP), distE(m17, i18) + 1e-4f);
                o[fo + 11] = distE(tT, m5);
            }
            // ---- joint angles k=10..14 ----
            #pragma unroll
            for (int k = 10; k < 15; ++k) {
                float3 vp = sp(fr, b + cP[k]);
                float3 vj = sp(fr, b + cJ[k]);
                float3 vc = sp(fr, b + cC[k]);
                float3 v1 = f3sub(vp, vj), v2 = f3sub(vc, vj);
                float den = sqrtf(f3dot(v1, v1) * f3dot(v2, v2)) + 1e-6f;
                o[34 + h * 15 + k] = acosc(fdiv(f3dot(v1, v2), den));
            }
        } else {
            // ---- spreads 0..2 ----
            {
                float3 v5  = f3sub(sp(fr, b + 5),  wH);
                float3 v9  = f3sub(sp(fr, b + 9),  wH);
                float3 v13 = f3sub(sp(fr, b + 13), wH);
                float3 v17 = f3sub(sp(fr, b + 17), wH);
                o[70 + h * 3 + 0] = acosc(fdiv(f3dot(v5,  v9 ), sqrtf(f3dot(v5,  v5 ) * f3dot(v9,  v9 )) + 1e-6f));
                o[70 + h * 3 + 1] = acosc(fdiv(f3dot(v9,  v13), sqrtf(f3dot(v9,  v9 ) * f3dot(v13, v13)) + 1e-6f));
                o[70 + h * 3 + 2] = acosc(fdiv(f3dot(v13, v17), sqrtf(f3dot(v13, v13) * f3dot(v17, v17)) + 1e-6f));
                // ---- palm normal + up/fwd (reuses v5, v17) ----
                float3 n = f3cross(v5, v17);
                float inv = fdiv(1.0f, f3norm(n) + 1e-6f);
                n = f3scale(n, inv);
                o[64 + h * 3 + 0] = n.x;
                o[64 + h * 3 + 1] = n.y;
                o[64 + h * 3 + 2] = n.z;
                o[76 + h * 2 + 0] = n.y;
                o[76 + h * 2 + 1] = n.z;
            }

            // ---- temporal ----
            float3 vh = velH(sHalo, t0, t, h);
            float nh = f3norm(vh);
            {
                float ih = fdiv(1.0f, fmaxf(nh, 1e-6f));
                o[80 + h * 3 + 0] = vh.x * ih;
                o[80 + h * 3 + 1] = vh.y * ih;
                o[80 + h * 3 + 2] = vh.z * ih;
                o[98 + h] = nh;
            }
            {
                float3 vhn = velH(sHalo, t0, t + 1, h);
                float3 a  = f3scale(vh,  fdiv(1.0f, nh + 1e-6f));
                float3 bb = f3scale(vhn, fdiv(1.0f, f3norm(vhn) + 1e-6f));
                o[86 + h] = (t == TT - 1) ? 0.0f : acosc(f3dot(a, bb));
            }
            {
                int td = t < 1 ? 1 : (t > TT - 2 ? TT - 2 : t);
                float dp = f3norm(f3sub(hp(sHalo, t0, td + 1, h), hp(sHalo, t0, td + 1, 2)));
                float dm = f3norm(f3sub(hp(sHalo, t0, td - 1, h), hp(sHalo, t0, td - 1, 2)));
                o[91 + h] = 0.5f * (dp - dm);
            }
            {
                int tc = t < 1 ? 1 : (t > TT - 2 ? TT - 2 : t);
                float3 ap = velH(sHalo, t0, tc + 1, h);
                float3 am = velH(sHalo, t0, tc - 1, h);
                float3 ac = make_float3(0.5f*(ap.x-am.x), 0.5f*(ap.y-am.y), 0.5f*(ap.z-am.z));
                o[100 + h] = f3norm(ac);
            }
        }
    }

    __syncthreads();

    // ---- coalesced writeback ----
    int nvalid = BT - f0;
    if (nvalid > NF) nvalid = NF;
    if (nvalid <= 0) return;
    const size_t obase = (size_t)f0 * FPF;
    const int total = nvalid * FPF;
    for (int i = tid; i < total; i += BLK) {
        out[obase + i] = sOut[i + i / FPF];
    }
}

extern "C" void kernel_launch(void* const* d_in, const int* in_sizes, int n_in,
                              void* d_out, int out_size)
{
    const float* xyz = (const float*)d_in[0];
    const float* fm  = (const float*)d_in[1];
    const float* bm  = (const float*)d_in[2];
    float* out = (float*)d_out;

    const int BT = in_sizes[1];
    const int blocks = (BT + NF - 1) / NF;

    const int smem_bytes = (NF * FST + HROWS * 9 + NF * SP) * (int)sizeof(float);
    cudaFuncSetAttribute(geo_kernel, cudaFuncAttributeMaxDynamicSharedMemorySize, smem_bytes);

    geo_kernel<<<blocks, BLK, smem_bytes>>>(xyz, fm, bm, out, BT);
}

// round 8
// speedup vs baseline: 6.2688x; 1.2962x over previous
#include <cuda_runtime.h>
#include <math.h>

#define TT   512      // frames per batch
#define NLM  51       // landmarks
#define FST  153      // floats per frame (51*3)
#define FPF  114      // features per frame
#define SP   115      // padded out-stage stride (odd -> conflict-free)
#define NF   32       // frames per block
#define BLK  256      // threads per block (8 threads / frame)
#define HROWS 36      // NF + 4 halo rows

__device__ __forceinline__ float fsqrt_a(float x){
    float r; asm("sqrt.approx.f32 %0, %1;" : "=f"(r) : "f"(x)); return r;
}

__device__ __forceinline__ float3 f3sub(float3 a, float3 b){ return make_float3(a.x-b.x, a.y-b.y, a.z-b.z); }
__device__ __forceinline__ float3 f3add(float3 a, float3 b){ return make_float3(a.x+b.x, a.y+b.y, a.z+b.z); }
__device__ __forceinline__ float3 f3scale(float3 a, float s){ return make_float3(a.x*s, a.y*s, a.z*s); }
__device__ __forceinline__ float  f3dot(float3 a, float3 b){ return a.x*b.x + a.y*b.y + a.z*b.z; }
__device__ __forceinline__ float3 f3cross(float3 a, float3 b){
    return make_float3(a.y*b.z - a.z*b.y, a.z*b.x - a.x*b.z, a.x*b.y - a.y*b.x);
}
__device__ __forceinline__ float f3norm(float3 v){ return fsqrt_a(f3dot(v,v)); }
__device__ __forceinline__ float distE(float3 a, float3 b){ float3 d = f3sub(a,b); return fsqrt_a(f3dot(d,d) + 1e-6f); }
__device__ __forceinline__ float fdiv(float a, float b){ return __fdividef(a, b); }

// fast acos: A&S 4.4.45 7-term poly, |err| ~ 2e-8 rad; clip matches reference
__device__ __forceinline__ float acosc(float c){
    c = fminf(fmaxf(c, -1.0f + 1e-6f), 1.0f - 1e-6f);
    float ax = fabsf(c);
    float p = -0.0012624911f;
    p = fmaf(p, ax,  0.0066700901f);
    p = fmaf(p, ax, -0.0170881256f);
    p = fmaf(p, ax,  0.0308918810f);
    p = fmaf(p, ax, -0.0501743046f);
    p = fmaf(p, ax,  0.0889789874f);
    p = fmaf(p, ax, -0.2145988016f);
    p = fmaf(p, ax,  1.5707963050f);
    float r = fsqrt_a(1.0f - ax) * p;
    return (c < 0.0f) ? (3.14159265358979f - r) : r;
}

__device__ __forceinline__ float3 sp(const float* __restrict__ sF, int lm){
    return make_float3(sF[lm*3], sF[lm*3+1], sF[lm*3+2]);
}
// halo read: lmsel 0->wrist0, 1->wrist21, 2->nose(42); tau in [0,TT-1]
__device__ __forceinline__ float3 hp(const float* __restrict__ sH, int t0, int tau, int lmsel){
    const float* q = sH + (tau - t0 + 2) * 9 + lmsel * 3;
    return make_float3(q[0], q[1], q[2]);
}
__device__ __forceinline__ float3 velH(const float* __restrict__ sH, int t0, int t, int lmsel){
    int tc = t < 1 ? 1 : (t > TT - 2 ? TT - 2 : t);
    float3 a = hp(sH, t0, tc + 1, lmsel);
    float3 c = hp(sH, t0, tc - 1, lmsel);
    return make_float3(0.5f*(a.x-c.x), 0.5f*(a.y-c.y), 0.5f*(a.z-c.z));
}

__constant__ int cP[15] = {0,1,2, 0,5,6, 0,9,10, 0,13,14, 0,17,18};
__constant__ int cJ[15] = {1,2,3, 5,6,7, 9,10,11, 13,14,15, 17,18,19};
__constant__ int cC[15] = {2,3,4, 6,7,8, 10,11,12, 14,15,16, 18,19,20};

extern __shared__ float smem_raw[];

__global__ void __launch_bounds__(BLK, 5)
geo_kernel(const float* __restrict__ xyz,
           const float* __restrict__ fmask,
           const float* __restrict__ bmask,
           float* __restrict__ out,
           int BT)
{
    float* sIn   = smem_raw;                 // NF*153
    float* sHalo = sIn + NF * FST;           // 36*9
    float* sOut  = sHalo + HROWS * 9;        // NF*115

    const int tid = threadIdx.x;
    const int f   = tid & (NF - 1);          // frame within block
    const int sub = tid >> 5;                // 0..7, whole warps
    const int f0  = blockIdx.x * NF;
    const int bt  = f0 + f;

    const int bi = f0 / TT;
    const int t0 = f0 - bi * TT;

    // ---- stage input frames (coalesced float4) ----
    {
        const float4* gsrc = (const float4*)(xyz + (size_t)f0 * FST);
        float4* sdst = (float4*)sIn;
        #pragma unroll
        for (int i = tid; i < (NF * FST) / 4; i += BLK) sdst[i] = gsrc[i];
    }
    // ---- stage temporal halo ----
    {
        const float* xb = xyz + (size_t)bi * TT * FST;
        for (int i = tid; i < HROWS * 9; i += BLK) {
            int row = i / 9, c = i - row * 9;
            int lmsel = c / 3;
            int lm = (lmsel == 0) ? 0 : (lmsel == 1 ? 21 : 42);
            int tl = t0 - 2 + row;
            tl = tl < 0 ? 0 : (tl > TT - 1 ? TT - 1 : tl);
            sHalo[i] = __ldg(xb + (size_t)tl * FST + lm * 3 + (c - lmsel * 3));
        }
    }
    __syncthreads();

    if (bt < BT) {
        const float* fr = sIn + f * FST;
        float* o = sOut + f * SP;
        const int t = t0 + f;
        const int h    = sub >> 2;           // hand
        const int part = sub & 3;            // 4-way split within hand
        const int b  = h * 21;
        const int fo = h * 12;

        const float3 w0 = sp(fr, 0);
        const float3 w1 = sp(fr, 21);
        const float3 wH = (h == 0) ? w0 : w1;

        if (part == 0) {
            // ---- tips + cross ----
            float3 tT = sp(fr, b + 4),  tI = sp(fr, b + 8),  tM = sp(fr, b + 12);
            float3 tR = sp(fr, b + 16), tP = sp(fr, b + 20);
            o[fo + 0] = distE(tT, tI);
            o[fo + 1] = distE(tI, tM);
            o[fo + 2] = distE(tM, tR);
            o[fo + 3] = distE(tR, tP);
            o[fo + 4] = distE(tT, tP);
            o[fo + 10] = tI.x - tM.x;

            // ---- joint angles k=0..4 ----
            #pragma unroll
            for (int k = 0; k < 5; ++k) {
                float3 vp = sp(fr, b + cP[k]);
                float3 vj = sp(fr, b + cJ[k]);
                float3 vc = sp(fr, b + cC[k]);
                float3 v1 = f3sub(vp, vj), v2 = f3sub(vc, vj);
                float den = fsqrt_a(f3dot(v1, v1) * f3dot(v2, v2)) + 1e-6f;
                o[34 + h * 15 + k] = acosc(fdiv(f3dot(v1, v2), den));
            }

            // ---- body block (masked) ----
            const float bg = __ldg(bmask + bt);
            float3 lsh = sp(fr, 45), rsh = sp(fr, 46);
            float shmx = 0.5f * (lsh.x + rsh.x);
            float shmy = 0.5f * (lsh.y + rsh.y);
            float shw  = distE(lsh, rsh);
            float si   = fdiv(1.0f, shw + 1e-6f);
            float3 mo = f3scale(f3add(sp(fr, 49), sp(fr, 50)), 0.5f);
            if (h == 0) {
                float3 lel = sp(fr, 47);
                o[103] = (w0.y - shmy) * si * bg;
                o[104] = (w0.x - shmx) * si * bg;
                o[105] = distE(w0, lsh) * bg;
                o[106] = distE(w0, lel) * bg;
                o[111] = shw * bg;
                o[112] = distE(w0, mo) * bg;
            } else {
                float3 rel = sp(fr, 48);
                o[107] = (w1.y - shmy) * si * bg;
                o[108] = (w1.x - shmx) * si * bg;
                o[109] = distE(w1, rsh) * bg;
                o[110] = distE(w1, rel) * bg;
                o[113] = distE(w1, mo) * bg;
            }
        } else if (part == 1) {
            // ---- joint angles k=5..9 ----
            #pragma unroll
            for (int k = 5; k < 10; ++k) {
                float3 vp = sp(fr, b + cP[k]);
                float3 vj = sp(fr, b + cJ[k]);
                float3 vc = sp(fr, b + cC[k]);
                float3 v1 = f3sub(vp, vj), v2 = f3sub(vc, vj);
                float den = fsqrt_a(f3dot(v1, v1) * f3dot(v2, v2)) + 1e-6f;
                o[34 + h * 15 + k] = acosc(fdiv(f3dot(v1, v2), den));
            }

            // ---- face half (masked) ----
            {
                const float fg = __ldg(fmask + bt);
                const float3 nose = sp(fr, 42);
                const float3 chin = sp(fr, 43);
                const float3 fh   = sp(fr, 44);
                const float3 tip  = (h == 0) ? sp(fr, 8) : sp(fr, 29);
                o[24 + h * 3 + 0] = distE(wH, nose) * fg;
                o[24 + h * 3 + 1] = distE(wH, chin) * fg;
                o[24 + h * 3 + 2] = distE(wH, fh)   * fg;
                o[30 + h * 2 + 0] = distE(tip, nose) * fg;
                o[30 + h * 2 + 1] = distE(tip, fh)   * fg;
            }

            // ---- x diffs ----
            o[93 + h * 2] = fr[(b + 8)  * 3] - fr[(b + 12) * 3];
            o[94 + h * 2] = fr[(b + 12) * 3] - fr[(b + 16) * 3];

            if (h == 0) {
                // inter-hand + sigmoid
                o[88] = distE(w0, w1);
                float3 rel = f3sub(w1, w0);
                float rnv = f3norm(rel);
                float ri = fdiv(1.0f, rnv + 1e-6f);
                o[89] = rel.x * ri;
                o[90] = rel.y * ri;
                float xs = 0.25f - 5.0f * rnv;
                o[102] = fdiv(1.0f, 1.0f + __expf(-xs));
            } else {
                // ld . rd
                float3 v0 = velH(sHalo, t0, t, 0);
                float3 v1 = velH(sHalo, t0, t, 1);
                float3 a0 = f3scale(v0, fdiv(1.0f, f3norm(v0) + 1e-6f));
                float3 a1 = f3scale(v1, fdiv(1.0f, f3norm(v1) + 1e-6f));
                o[97] = f3dot(a0, a1);
            }
        } else if (part == 2) {
            // ---- curls + d_ti ----
            {
                float3 tT = sp(fr, b + 4),  tI = sp(fr, b + 8),  tM = sp(fr, b + 12);
                float3 tR = sp(fr, b + 16), tP = sp(fr, b + 20);
                float3 m2  = sp(fr, b + 2),  m5  = sp(fr, b + 5),  m9  = sp(fr, b + 9);
                float3 m13 = sp(fr, b + 13), m17 = sp(fr, b + 17);
                float3 i3  = sp(fr, b + 3),  i6  = sp(fr, b + 6),  i10 = sp(fr, b + 10);
                float3 i14 = sp(fr, b + 14), i18 = sp(fr, b + 18);
                o[fo + 5] = fdiv(distE(m2,  tT), distE(m2,  i3)  + 1e-4f);
                o[fo + 6] = fdiv(distE(m5,  tI), distE(m5,  i6)  + 1e-4f);
                o[fo + 7] = fdiv(distE(m9,  tM), distE(m9,  i10) + 1e-4f);
                o[fo + 8] = fdiv(distE(m13, tR), distE(m13, i14) + 1e-4f);
                o[fo + 9] = fdiv(distE(m17, tP), distE(m17, i18) + 1e-4f);
                o[fo + 11] = distE(tT, m5);
            }
            // ---- joint angles k=10..14 ----
            #pragma unroll
            for (int k = 10; k < 15; ++k) {
                float3 vp = sp(fr, b + cP[k]);
                float3 vj = sp(fr, b + cJ[k]);
                float3 vc = sp(fr, b + cC[k]);
                float3 v1 = f3sub(vp, vj), v2 = f3sub(vc, vj);
                float den = fsqrt_a(f3dot(v1, v1) * f3dot(v2, v2)) + 1e-6f;
                o[34 + h * 15 + k] = acosc(fdiv(f3dot(v1, v2), den));
            }
        } else {
            // ---- spreads 0..2 ----
            {
                float3 v5  = f3sub(sp(fr, b + 5),  wH);
                float3 v9  = f3sub(sp(fr, b + 9),  wH);
                float3 v13 = f3sub(sp(fr, b + 13), wH);
                float3 v17 = f3sub(sp(fr, b + 17), wH);
                o[70 + h * 3 + 0] = acosc(fdiv(f3dot(v5,  v9 ), fsqrt_a(f3dot(v5,  v5 ) * f3dot(v9,  v9 )) + 1e-6f));
                o[70 + h * 3 + 1] = acosc(fdiv(f3dot(v9,  v13), fsqrt_a(f3dot(v9,  v9 ) * f3dot(v13, v13)) + 1e-6f));
                o[70 + h * 3 + 2] = acosc(fdiv(f3dot(v13, v17), fsqrt_a(f3dot(v13, v13) * f3dot(v17, v17)) + 1e-6f));
                // ---- palm normal + up/fwd (reuses v5, v17) ----
                float3 n = f3cross(v5, v17);
                float inv = fdiv(1.0f, f3norm(n) + 1e-6f);
                n = f3scale(n, inv);
                o[64 + h * 3 + 0] = n.x;
                o[64 + h * 3 + 1] = n.y;
                o[64 + h * 3 + 2] = n.z;
                o[76 + h * 2 + 0] = n.y;
                o[76 + h * 2 + 1] = n.z;
            }

            // ---- temporal ----
            float3 vh = velH(sHalo, t0, t, h);
            float nh = f3norm(vh);
            {
                float ih = fdiv(1.0f, fmaxf(nh, 1e-6f));
                o[80 + h * 3 + 0] = vh.x * ih;
                o[80 + h * 3 + 1] = vh.y * ih;
                o[80 + h * 3 + 2] = vh.z * ih;
                o[98 + h] = nh;
            }
            {
                float3 vhn = velH(sHalo, t0, t + 1, h);
                float3 a  = f3scale(vh,  fdiv(1.0f, nh + 1e-6f));
                float3 bb = f3scale(vhn, fdiv(1.0f, f3norm(vhn) + 1e-6f));
                o[86 + h] = (t == TT - 1) ? 0.0f : acosc(f3dot(a, bb));
            }
            {
                int td = t < 1 ? 1 : (t > TT - 2 ? TT - 2 : t);
                float dp = f3norm(f3sub(hp(sHalo, t0, td + 1, h), hp(sHalo, t0, td + 1, 2)));
                float dm = f3norm(f3sub(hp(sHalo, t0, td - 1, h), hp(sHalo, t0, td - 1, 2)));
                o[91 + h] = 0.5f * (dp - dm);
            }
            {
                int tc = t < 1 ? 1 : (t > TT - 2 ? TT - 2 : t);
                float3 ap = velH(sHalo, t0, tc + 1, h);
                float3 am = velH(sHalo, t0, tc - 1, h);
                float3 ac = make_float3(0.5f*(ap.x-am.x), 0.5f*(ap.y-am.y), 0.5f*(ap.z-am.z));
                o[100 + h] = f3norm(ac);
            }
        }
    }

    __syncthreads();

    // ---- coalesced writeback ----
    int nvalid = BT - f0;
    if (nvalid > NF) nvalid = NF;
    if (nvalid <= 0) return;
    const size_t obase = (size_t)f0 * FPF;
    const int total = nvalid * FPF;
    for (int i = tid; i < total; i += BLK) {
        out[obase + i] = sOut[i + i / FPF];
    }
}

extern "C" void kernel_launch(void* const* d_in, const int* in_sizes, int n_in,
                              void* d_out, int out_size)
{
    const float* xyz = (const float*)d_in[0];
    const float* fm  = (const float*)d_in[1];
    const float* bm  = (const float*)d_in[2];
    float* out = (float*)d_out;

    const int BT = in_sizes[1];
    const int blocks = (BT + NF - 1) / NF;

    const int smem_bytes = (NF * FST + HROWS * 9 + NF * SP) * (int)sizeof(float);
    cudaFuncSetAttribute(geo_kernel, cudaFuncAttributeMaxDynamicSharedMemorySize, smem_bytes);

    geo_kernel<<<blocks, BLK, smem_bytes>>>(xyz, fm, bm, out, BT);
}